// round 1
// baseline (speedup 1.0000x reference)
#include <cuda_runtime.h>
#include <cstddef>

// ---------------------------------------------------------------------------
// MEGNet-style block:
//   e_out = MLP_e(concat(edge, nf[src], nf[dst], g[e2g]))        [E,32]
//   h     = segment_sum(e_out, dst, N)                            [N,32]
//   n_out = MLP_n(concat(nf, h, g[n2g]))                          [N,32]
//   e_comb= segment_sum(e_out, e2g, B); n_comb = segsum(n_out,n2g)
//   g_out = MLP_u(concat(n_comb, e_comb, g))                      [B,32]
// Output: concat(e_out, n_out, g_out) fp32.
// ---------------------------------------------------------------------------

#define NMAX 50000
#define BMAX 64

__device__ __align__(16) float d_hbuf[(size_t)NMAX * 32];
__device__ __align__(16) float d_ecomb[BMAX * 32];
__device__ __align__(16) float d_ncomb[BMAX * 32];

// ---------------------------------------------------------------------------
__global__ void zero_kernel(int n_h, int n_c) {
    int stride = gridDim.x * blockDim.x;
    for (int i = blockIdx.x * blockDim.x + threadIdx.x; i < n_h; i += stride)
        d_hbuf[i] = 0.0f;
    int i = blockIdx.x * blockDim.x + threadIdx.x;
    if (i < n_c) { d_ecomb[i] = 0.0f; d_ncomb[i] = 0.0f; }
}

// Accumulate one 32-wide input segment into 64 hidden accumulators.
// x: 32 contiguous fp32 (16B aligned), w: &sW1[seg*32*64] row-major [k][j].
__device__ __forceinline__ void mlp1_seg(const float* __restrict__ x,
                                         const float* __restrict__ w,
                                         float* __restrict__ h) {
    float4 xv[8];
#pragma unroll
    for (int q = 0; q < 8; q++) xv[q] = reinterpret_cast<const float4*>(x)[q];
#pragma unroll
    for (int q = 0; q < 8; q++) {
#pragma unroll
        for (int c = 0; c < 4; c++) {
            float xk = reinterpret_cast<const float*>(&xv[q])[c];
            const float4* wr = reinterpret_cast<const float4*>(w + (q * 4 + c) * 64);
#pragma unroll
            for (int j = 0; j < 16; j++) {
                float4 wv = wr[j];
                h[j * 4 + 0] = fmaf(xk, wv.x, h[j * 4 + 0]);
                h[j * 4 + 1] = fmaf(xk, wv.y, h[j * 4 + 1]);
                h[j * 4 + 2] = fmaf(xk, wv.z, h[j * 4 + 2]);
                h[j * 4 + 3] = fmaf(xk, wv.w, h[j * 4 + 3]);
            }
        }
    }
}

// out[32] = b2 + relu(h[64]) @ W2[64,32]
__device__ __forceinline__ void mlp2(const float* __restrict__ h,
                                     const float* __restrict__ w2,
                                     const float* __restrict__ b2,
                                     float* __restrict__ out) {
#pragma unroll
    for (int j = 0; j < 32; j++) out[j] = b2[j];
#pragma unroll
    for (int k = 0; k < 64; k++) {
        float hk = fmaxf(h[k], 0.0f);
        const float4* wr = reinterpret_cast<const float4*>(w2 + k * 32);
#pragma unroll
        for (int j = 0; j < 8; j++) {
            float4 wv = wr[j];
            out[j * 4 + 0] = fmaf(hk, wv.x, out[j * 4 + 0]);
            out[j * 4 + 1] = fmaf(hk, wv.y, out[j * 4 + 1]);
            out[j * 4 + 2] = fmaf(hk, wv.z, out[j * 4 + 2]);
            out[j * 4 + 3] = fmaf(hk, wv.w, out[j * 4 + 3]);
        }
    }
}

// ---------------------------------------------------------------------------
// Edge MLP + fused scatter (h into dst nodes, e_comb per graph) + e_out store.
// One thread per edge.
// ---------------------------------------------------------------------------
__global__ __launch_bounds__(256) void edge_kernel(
    const float* __restrict__ edge_feat, const float* __restrict__ node_feat,
    const float* __restrict__ g_repr, const int* __restrict__ src,
    const int* __restrict__ dst, const int* __restrict__ e2g,
    const float* __restrict__ W1, const float* __restrict__ b1,
    const float* __restrict__ W2, const float* __restrict__ b2,
    float* __restrict__ e_out, int E) {
    __shared__ float sW1[128 * 64];
    __shared__ float sW2[64 * 32];
    __shared__ float sb1[64];
    __shared__ float sb2[32];
    for (int i = threadIdx.x; i < 128 * 64; i += 256) sW1[i] = W1[i];
    for (int i = threadIdx.x; i < 64 * 32; i += 256) sW2[i] = W2[i];
    if (threadIdx.x < 64) sb1[threadIdx.x] = b1[threadIdx.x];
    if (threadIdx.x < 32) sb2[threadIdx.x] = b2[threadIdx.x];
    __syncthreads();

    int e = blockIdx.x * 256 + threadIdx.x;
    if (e >= E) return;

    int s = src[e];
    int d = dst[e];
    int g = e2g[e];

    float h[64];
#pragma unroll
    for (int j = 0; j < 64; j++) h[j] = sb1[j];

    mlp1_seg(edge_feat + (size_t)e * 32, sW1 + 0 * 32 * 64, h);
    mlp1_seg(node_feat + (size_t)s * 32, sW1 + 1 * 32 * 64, h);
    mlp1_seg(node_feat + (size_t)d * 32, sW1 + 2 * 32 * 64, h);
    mlp1_seg(g_repr + (size_t)g * 32, sW1 + 3 * 32 * 64, h);

    float out[32];
    mlp2(h, sW2, sb2, out);

    // store e_out (float4)
    float4* op = reinterpret_cast<float4*>(e_out + (size_t)e * 32);
#pragma unroll
    for (int q = 0; q < 8; q++) {
        float4 v;
        v.x = out[q * 4 + 0]; v.y = out[q * 4 + 1];
        v.z = out[q * 4 + 2]; v.w = out[q * 4 + 3];
        op[q] = v;
    }

    // scatter into h (per-dst-node) and e_comb (per-graph)
    float* hb = d_hbuf + (size_t)d * 32;
    float* ec = d_ecomb + g * 32;
#pragma unroll
    for (int j = 0; j < 32; j++) {
        atomicAdd(hb + j, out[j]);
        atomicAdd(ec + j, out[j]);
    }
}

// ---------------------------------------------------------------------------
// Node MLP + fused n_comb scatter. One thread per node.
// ---------------------------------------------------------------------------
__global__ __launch_bounds__(256) void node_kernel(
    const float* __restrict__ node_feat, const float* __restrict__ g_repr,
    const int* __restrict__ n2g, const float* __restrict__ W1,
    const float* __restrict__ b1, const float* __restrict__ W2,
    const float* __restrict__ b2, float* __restrict__ n_out, int N) {
    __shared__ float sW1[96 * 64];
    __shared__ float sW2[64 * 32];
    __shared__ float sb1[64];
    __shared__ float sb2[32];
    for (int i = threadIdx.x; i < 96 * 64; i += 256) sW1[i] = W1[i];
    for (int i = threadIdx.x; i < 64 * 32; i += 256) sW2[i] = W2[i];
    if (threadIdx.x < 64) sb1[threadIdx.x] = b1[threadIdx.x];
    if (threadIdx.x < 32) sb2[threadIdx.x] = b2[threadIdx.x];
    __syncthreads();

    int n = blockIdx.x * 256 + threadIdx.x;
    if (n >= N) return;

    int g = n2g[n];

    float h[64];
#pragma unroll
    for (int j = 0; j < 64; j++) h[j] = sb1[j];

    mlp1_seg(node_feat + (size_t)n * 32, sW1 + 0 * 32 * 64, h);
    mlp1_seg(d_hbuf + (size_t)n * 32, sW1 + 1 * 32 * 64, h);
    mlp1_seg(g_repr + (size_t)g * 32, sW1 + 2 * 32 * 64, h);

    float out[32];
    mlp2(h, sW2, sb2, out);

    float4* op = reinterpret_cast<float4*>(n_out + (size_t)n * 32);
#pragma unroll
    for (int q = 0; q < 8; q++) {
        float4 v;
        v.x = out[q * 4 + 0]; v.y = out[q * 4 + 1];
        v.z = out[q * 4 + 2]; v.w = out[q * 4 + 3];
        op[q] = v;
    }

    float* nc = d_ncomb + g * 32;
#pragma unroll
    for (int j = 0; j < 32; j++) atomicAdd(nc + j, out[j]);
}

// ---------------------------------------------------------------------------
// Global MLP: u_inp = concat(n_comb, e_comb, g_repr) [B,96] -> [B,32].
// One block, B*64 threads.
// ---------------------------------------------------------------------------
__global__ void global_kernel(const float* __restrict__ g_repr,
                              const float* __restrict__ W1,
                              const float* __restrict__ b1,
                              const float* __restrict__ W2,
                              const float* __restrict__ b2,
                              float* __restrict__ g_out, int B) {
    __shared__ float u[BMAX * 96];
    __shared__ float hh[BMAX * 64];
    int tid = threadIdx.x;
    for (int i = tid; i < B * 32; i += blockDim.x) {
        int r = i / 32, j = i % 32;
        u[r * 96 + j] = d_ncomb[i];
        u[r * 96 + 32 + j] = d_ecomb[i];
        u[r * 96 + 64 + j] = g_repr[i];
    }
    __syncthreads();
    if (tid < B * 64) {
        int r = tid / 64, j = tid % 64;
        float acc = b1[j];
        for (int k = 0; k < 96; k++) acc = fmaf(u[r * 96 + k], W1[k * 64 + j], acc);
        hh[r * 64 + j] = fmaxf(acc, 0.0f);
    }
    __syncthreads();
    if (tid < B * 32) {
        int r = tid / 32, j = tid % 32;
        float acc = b2[j];
        for (int k = 0; k < 64; k++) acc = fmaf(hh[r * 64 + k], W2[k * 32 + j], acc);
        g_out[tid] = acc;
    }
}

// ---------------------------------------------------------------------------
extern "C" void kernel_launch(void* const* d_in, const int* in_sizes, int n_in,
                              void* d_out, int out_size) {
    const float* edge_feat = (const float*)d_in[0];
    const float* node_feat = (const float*)d_in[1];
    const float* g_repr    = (const float*)d_in[2];
    const int*   src       = (const int*)d_in[3];
    const int*   dst       = (const int*)d_in[4];
    const int*   n2g       = (const int*)d_in[5];
    const int*   e2g       = (const int*)d_in[6];
    const float* W_e1 = (const float*)d_in[7];
    const float* b_e1 = (const float*)d_in[8];
    const float* W_e2 = (const float*)d_in[9];
    const float* b_e2 = (const float*)d_in[10];
    const float* W_n1 = (const float*)d_in[11];
    const float* b_n1 = (const float*)d_in[12];
    const float* W_n2 = (const float*)d_in[13];
    const float* b_n2 = (const float*)d_in[14];
    const float* W_u1 = (const float*)d_in[15];
    const float* b_u1 = (const float*)d_in[16];
    const float* W_u2 = (const float*)d_in[17];
    const float* b_u2 = (const float*)d_in[18];

    int E = in_sizes[3];       // src
    int N = in_sizes[5];       // node2graph
    int B = in_sizes[2] / 32;  // g_repr rows

    float* e_out = (float*)d_out;
    float* n_out = e_out + (size_t)E * 32;
    float* g_out = n_out + (size_t)N * 32;

    zero_kernel<<<2048, 256>>>(N * 32, B * 32);
    edge_kernel<<<(E + 255) / 256, 256>>>(edge_feat, node_feat, g_repr, src,
                                          dst, e2g, W_e1, b_e1, W_e2, b_e2,
                                          e_out, E);
    node_kernel<<<(N + 255) / 256, 256>>>(node_feat, g_repr, n2g, W_n1, b_n1,
                                          W_n2, b_n2, n_out, N);
    global_kernel<<<1, B * 64>>>(g_repr, W_u1, b_u1, W_u2, b_u2, g_out, B);
}

// round 4
// speedup vs baseline: 27.1025x; 27.1025x over previous
#include <cuda_runtime.h>
#include <cstddef>

// MEGNet-style block, tile-GEMM formulation.
//   e_out = MLP_e(concat(edge, nf[src], nf[dst], g[e2g]))   [E,32]
//   h     = segsum(e_out, dst, N)
//   n_out = MLP_n(concat(nf, h, g[n2g]))                    [N,32]
//   e_comb= segsum(e_out, e2g, B); n_comb = segsum(n_out, n2g)
//   g_out = MLP_u(concat(n_comb, e_comb, g))                [B,32]

#define NMAX 50000
#define BMAX 64
#define TILE 128

__device__ __align__(16) float d_hbuf[(size_t)NMAX * 32];
__device__ __align__(16) float d_ecomb[BMAX * 32];
__device__ __align__(16) float d_ncomb[BMAX * 32];

__global__ void zero_kernel(int n_h, int n_c) {
    int stride = gridDim.x * blockDim.x;
    for (int i = blockIdx.x * blockDim.x + threadIdx.x; i < n_h; i += stride)
        d_hbuf[i] = 0.0f;
    int i = blockIdx.x * blockDim.x + threadIdx.x;
    if (i < n_c) { d_ecomb[i] = 0.0f; d_ncomb[i] = 0.0f; }
}

// ---------------------------------------------------------------------------
// Edge kernel: per 128-edge tile.
// SMEM layout (dynamic):
//   X  [128][132]  (67584 B)   -> overlaid later: H [128][68] then S [128][32]
//   W1 [128][64]   (32768 B)
//   W2 [64][32]    ( 8192 B)
//   b1[64] b2[32]  (  384 B)
//   idx[3*128] int ( 1536 B)
// total 110464 B
// ---------------------------------------------------------------------------
__global__ __launch_bounds__(256) void edge_kernel(
    const float* __restrict__ edge_feat, const float* __restrict__ node_feat,
    const float* __restrict__ g_repr, const int* __restrict__ src,
    const int* __restrict__ dst, const int* __restrict__ e2g,
    const float* __restrict__ W1, const float* __restrict__ b1,
    const float* __restrict__ W2, const float* __restrict__ b2,
    float* __restrict__ e_out, int E) {
    extern __shared__ float smem[];
    const int KPAD = 132;
    float* X   = smem;                 // 128*132 = 16896 floats
    float* W1s = X + 128 * KPAD;       // 8192
    float* W2s = W1s + 128 * 64;       // 2048
    float* b1s = W2s + 64 * 32;        // 64
    float* b2s = b1s + 64;             // 32
    int*   idx = (int*)(b2s + 32);     // 3*128 ints
    float* Hs  = X;                    // [128][68] = 8704 floats
    float* S   = X + 8704;             // [128][32] = 4096 floats

    const int tid = threadIdx.x;
    const int e0 = blockIdx.x * TILE;
    const int rows = min(TILE, E - e0);

    // indices
    for (int t = tid; t < rows; t += 256) {
        idx[t]            = src[e0 + t];
        idx[TILE + t]     = dst[e0 + t];
        idx[2 * TILE + t] = e2g[e0 + t];
    }
    // weights
    for (int t = tid; t < 128 * 64; t += 256) W1s[t] = W1[t];
    for (int t = tid; t < 64 * 32; t += 256) W2s[t] = W2[t];
    if (tid < 64) b1s[tid] = b1[tid];
    if (tid < 32) b2s[tid] = b2[tid];
    __syncthreads();

    // gather X rows: [edge | nf[src] | nf[dst] | g[e2g]]
    for (int p = tid; p < rows * 4; p += 256) {
        int r = p >> 2, s = p & 3;
        const float* sp;
        if (s == 0)      sp = edge_feat + (size_t)(e0 + r) * 32;
        else if (s == 1) sp = node_feat + (size_t)idx[r] * 32;
        else if (s == 2) sp = node_feat + (size_t)idx[TILE + r] * 32;
        else             sp = g_repr + (size_t)idx[2 * TILE + r] * 32;
        float* dp = X + r * KPAD + s * 32;
#pragma unroll
        for (int q = 0; q < 8; q++)
            ((float4*)dp)[q] = ((const float4*)sp)[q];
    }
    __syncthreads();

    // layer1: C1[128x64] = X[128x128] @ W1[128x64]; thread tile 4 rows x 8 cols
    const int tx = tid & 7;   // 8 col-groups of 8
    const int ty = tid >> 3;  // 32 row-groups of 4
    float acc[4][8];
#pragma unroll
    for (int i = 0; i < 4; i++)
#pragma unroll
        for (int c = 0; c < 8; c++) acc[i][c] = b1s[tx * 8 + c];

#pragma unroll 8
    for (int k = 0; k < 128; k++) {
        float a0 = X[(ty * 4 + 0) * KPAD + k];
        float a1 = X[(ty * 4 + 1) * KPAD + k];
        float a2 = X[(ty * 4 + 2) * KPAD + k];
        float a3 = X[(ty * 4 + 3) * KPAD + k];
        float4 w0 = *(const float4*)&W1s[k * 64 + tx * 8];
        float4 w1 = *(const float4*)&W1s[k * 64 + tx * 8 + 4];
        const float wv[8] = {w0.x, w0.y, w0.z, w0.w, w1.x, w1.y, w1.z, w1.w};
#pragma unroll
        for (int c = 0; c < 8; c++) {
            acc[0][c] = fmaf(a0, wv[c], acc[0][c]);
            acc[1][c] = fmaf(a1, wv[c], acc[1][c]);
            acc[2][c] = fmaf(a2, wv[c], acc[2][c]);
            acc[3][c] = fmaf(a3, wv[c], acc[3][c]);
        }
    }
    __syncthreads();  // all X reads done before overlay

    // relu -> Hs [row][68]
#pragma unroll
    for (int i = 0; i < 4; i++) {
        float* hp = Hs + (ty * 4 + i) * 68 + tx * 8;
#pragma unroll
        for (int c = 0; c < 8; c++) hp[c] = fmaxf(acc[i][c], 0.0f);
    }
    __syncthreads();

    // layer2: C2[128x32] = H[128x64] @ W2[64x32]; thread tile 4 rows x 4 cols
    const int tx2 = tid & 7;   // 8 col-groups of 4
    const int ty2 = tid >> 3;  // 32 row-groups of 4
    float acc2[4][4];
#pragma unroll
    for (int i = 0; i < 4; i++)
#pragma unroll
        for (int c = 0; c < 4; c++) acc2[i][c] = b2s[tx2 * 4 + c];

#pragma unroll 8
    for (int k = 0; k < 64; k++) {
        float a0 = Hs[(ty2 * 4 + 0) * 68 + k];
        float a1 = Hs[(ty2 * 4 + 1) * 68 + k];
        float a2 = Hs[(ty2 * 4 + 2) * 68 + k];
        float a3 = Hs[(ty2 * 4 + 3) * 68 + k];
        float4 w = *(const float4*)&W2s[k * 32 + tx2 * 4];
        const float wv[4] = {w.x, w.y, w.z, w.w};
#pragma unroll
        for (int c = 0; c < 4; c++) {
            acc2[0][c] = fmaf(a0, wv[c], acc2[0][c]);
            acc2[1][c] = fmaf(a1, wv[c], acc2[1][c]);
            acc2[2][c] = fmaf(a2, wv[c], acc2[2][c]);
            acc2[3][c] = fmaf(a3, wv[c], acc2[3][c]);
        }
    }
    // S does not overlap Hs -> no sync needed before writing
#pragma unroll
    for (int i = 0; i < 4; i++) {
        float4 v;
        v.x = acc2[i][0]; v.y = acc2[i][1]; v.z = acc2[i][2]; v.w = acc2[i][3];
        *(float4*)&S[(ty2 * 4 + i) * 32 + tx2 * 4] = v;
    }
    __syncthreads();

    // epilogue 1: coalesced e_out store
    for (int t = tid; t < rows * 8; t += 256) {
        int r = t >> 3, q = t & 7;
        ((float4*)(e_out + (size_t)(e0 + r) * 32))[q] = ((float4*)S)[r * 8 + q];
    }
    // epilogue 2: scatter into h (per-dst)
    for (int t = tid; t < rows * 32; t += 256) {
        int r = t >> 5, j = t & 31;
        atomicAdd(&d_hbuf[(size_t)idx[TILE + r] * 32 + j], S[r * 32 + j]);
    }
    // epilogue 3: block-reduced e_comb (e2g sorted -> few graphs per tile)
    if (tid < 32) {
        int g0 = idx[2 * TILE];
        int g1 = idx[2 * TILE + rows - 1];
        for (int g = g0; g <= g1; g++) {
            float s = 0.0f;
            for (int r = 0; r < rows; r++)
                if (idx[2 * TILE + r] == g) s += S[r * 32 + tid];
            atomicAdd(&d_ecomb[g * 32 + tid], s);
        }
    }
}

// ---------------------------------------------------------------------------
// Node kernel: K=96 (nf | h | g[n2g]); same structure. SMEM:
//   X [128][100] 51200 B (overlay H[128][68]=34816B then S at 34816, 16384B)
//   W1 [96][64] 24576 B, W2 8192 B, b 384 B, idx 512 B  -> total 84864 B
// ---------------------------------------------------------------------------
__global__ __launch_bounds__(256) void node_kernel(
    const float* __restrict__ node_feat, const float* __restrict__ g_repr,
    const int* __restrict__ n2g, const float* __restrict__ W1,
    const float* __restrict__ b1, const float* __restrict__ W2,
    const float* __restrict__ b2, float* __restrict__ n_out, int N) {
    extern __shared__ float smem[];
    const int KPAD = 100;
    float* X   = smem;               // 128*100 = 12800 floats
    float* W1s = X + 128 * KPAD;     // 6144
    float* W2s = W1s + 96 * 64;      // 2048
    float* b1s = W2s + 64 * 32;
    float* b2s = b1s + 64;
    int*   idx = (int*)(b2s + 32);   // n2g[128]
    float* Hs  = X;                  // [128][68]
    float* S   = X + 8704;           // [128][32]

    const int tid = threadIdx.x;
    const int n0 = blockIdx.x * TILE;
    const int rows = min(TILE, N - n0);

    for (int t = tid; t < rows; t += 256) idx[t] = n2g[n0 + t];
    for (int t = tid; t < 96 * 64; t += 256) W1s[t] = W1[t];
    for (int t = tid; t < 64 * 32; t += 256) W2s[t] = W2[t];
    if (tid < 64) b1s[tid] = b1[tid];
    if (tid < 32) b2s[tid] = b2[tid];
    __syncthreads();

    for (int p = tid; p < rows * 3; p += 256) {
        int r = p / 3, s = p % 3;
        const float* sp;
        if (s == 0)      sp = node_feat + (size_t)(n0 + r) * 32;
        else if (s == 1) sp = d_hbuf + (size_t)(n0 + r) * 32;
        else             sp = g_repr + (size_t)idx[r] * 32;
        float* dp = X + r * KPAD + s * 32;
#pragma unroll
        for (int q = 0; q < 8; q++)
            ((float4*)dp)[q] = ((const float4*)sp)[q];
    }
    __syncthreads();

    const int tx = tid & 7;
    const int ty = tid >> 3;
    float acc[4][8];
#pragma unroll
    for (int i = 0; i < 4; i++)
#pragma unroll
        for (int c = 0; c < 8; c++) acc[i][c] = b1s[tx * 8 + c];

#pragma unroll 8
    for (int k = 0; k < 96; k++) {
        float a0 = X[(ty * 4 + 0) * KPAD + k];
        float a1 = X[(ty * 4 + 1) * KPAD + k];
        float a2 = X[(ty * 4 + 2) * KPAD + k];
        float a3 = X[(ty * 4 + 3) * KPAD + k];
        float4 w0 = *(const float4*)&W1s[k * 64 + tx * 8];
        float4 w1 = *(const float4*)&W1s[k * 64 + tx * 8 + 4];
        const float wv[8] = {w0.x, w0.y, w0.z, w0.w, w1.x, w1.y, w1.z, w1.w};
#pragma unroll
        for (int c = 0; c < 8; c++) {
            acc[0][c] = fmaf(a0, wv[c], acc[0][c]);
            acc[1][c] = fmaf(a1, wv[c], acc[1][c]);
            acc[2][c] = fmaf(a2, wv[c], acc[2][c]);
            acc[3][c] = fmaf(a3, wv[c], acc[3][c]);
        }
    }
    __syncthreads();

#pragma unroll
    for (int i = 0; i < 4; i++) {
        float* hp = Hs + (ty * 4 + i) * 68 + tx * 8;
#pragma unroll
        for (int c = 0; c < 8; c++) hp[c] = fmaxf(acc[i][c], 0.0f);
    }
    __syncthreads();

    const int tx2 = tid & 7;
    const int ty2 = tid >> 3;
    float acc2[4][4];
#pragma unroll
    for (int i = 0; i < 4; i++)
#pragma unroll
        for (int c = 0; c < 4; c++) acc2[i][c] = b2s[tx2 * 4 + c];

#pragma unroll 8
    for (int k = 0; k < 64; k++) {
        float a0 = Hs[(ty2 * 4 + 0) * 68 + k];
        float a1 = Hs[(ty2 * 4 + 1) * 68 + k];
        float a2 = Hs[(ty2 * 4 + 2) * 68 + k];
        float a3 = Hs[(ty2 * 4 + 3) * 68 + k];
        float4 w = *(const float4*)&W2s[k * 32 + tx2 * 4];
        const float wv[4] = {w.x, w.y, w.z, w.w};
#pragma unroll
        for (int c = 0; c < 4; c++) {
            acc2[0][c] = fmaf(a0, wv[c], acc2[0][c]);
            acc2[1][c] = fmaf(a1, wv[c], acc2[1][c]);
            acc2[2][c] = fmaf(a2, wv[c], acc2[2][c]);
            acc2[3][c] = fmaf(a3, wv[c], acc2[3][c]);
        }
    }
#pragma unroll
    for (int i = 0; i < 4; i++) {
        float4 v;
        v.x = acc2[i][0]; v.y = acc2[i][1]; v.z = acc2[i][2]; v.w = acc2[i][3];
        *(float4*)&S[(ty2 * 4 + i) * 32 + tx2 * 4] = v;
    }
    __syncthreads();

    for (int t = tid; t < rows * 8; t += 256) {
        int r = t >> 3, q = t & 7;
        ((float4*)(n_out + (size_t)(n0 + r) * 32))[q] = ((float4*)S)[r * 8 + q];
    }
    if (tid < 32) {
        int g0 = idx[0];
        int g1 = idx[rows - 1];
        for (int g = g0; g <= g1; g++) {
            float s = 0.0f;
            for (int r = 0; r < rows; r++)
                if (idx[r] == g) s += S[r * 32 + tid];
            atomicAdd(&d_ncomb[g * 32 + tid], s);
        }
    }
}

// ---------------------------------------------------------------------------
__global__ void global_kernel(const float* __restrict__ g_repr,
                              const float* __restrict__ W1,
                              const float* __restrict__ b1,
                              const float* __restrict__ W2,
                              const float* __restrict__ b2,
                              float* __restrict__ g_out, int B) {
    __shared__ float u[BMAX * 96];
    __shared__ float hh[BMAX * 64];
    int tid = threadIdx.x;
    for (int i = tid; i < B * 32; i += blockDim.x) {
        int r = i / 32, j = i % 32;
        u[r * 96 + j] = d_ncomb[i];
        u[r * 96 + 32 + j] = d_ecomb[i];
        u[r * 96 + 64 + j] = g_repr[i];
    }
    __syncthreads();
    if (tid < B * 64) {
        int r = tid / 64, j = tid % 64;
        float acc = b1[j];
        for (int k = 0; k < 96; k++) acc = fmaf(u[r * 96 + k], W1[k * 64 + j], acc);
        hh[r * 64 + j] = fmaxf(acc, 0.0f);
    }
    __syncthreads();
    if (tid < B * 32) {
        int r = tid / 32, j = tid % 32;
        float acc = b2[j];
        for (int k = 0; k < 64; k++) acc = fmaf(hh[r * 64 + k], W2[k * 32 + j], acc);
        g_out[tid] = acc;
    }
}

// ---------------------------------------------------------------------------
extern "C" void kernel_launch(void* const* d_in, const int* in_sizes, int n_in,
                              void* d_out, int out_size) {
    const float* edge_feat = (const float*)d_in[0];
    const float* node_feat = (const float*)d_in[1];
    const float* g_repr    = (const float*)d_in[2];
    const int*   src       = (const int*)d_in[3];
    const int*   dst       = (const int*)d_in[4];
    const int*   n2g       = (const int*)d_in[5];
    const int*   e2g       = (const int*)d_in[6];
    const float* W_e1 = (const float*)d_in[7];
    const float* b_e1 = (const float*)d_in[8];
    const float* W_e2 = (const float*)d_in[9];
    const float* b_e2 = (const float*)d_in[10];
    const float* W_n1 = (const float*)d_in[11];
    const float* b_n1 = (const float*)d_in[12];
    const float* W_n2 = (const float*)d_in[13];
    const float* b_n2 = (const float*)d_in[14];
    const float* W_u1 = (const float*)d_in[15];
    const float* b_u1 = (const float*)d_in[16];
    const float* W_u2 = (const float*)d_in[17];
    const float* b_u2 = (const float*)d_in[18];

    int E = in_sizes[3];
    int N = in_sizes[5];
    int B = in_sizes[2] / 32;

    float* e_out = (float*)d_out;
    float* n_out = e_out + (size_t)E * 32;
    float* g_out = n_out + (size_t)N * 32;

    const int EDGE_SMEM = 110464;
    const int NODE_SMEM = 84864;
    cudaFuncSetAttribute(edge_kernel,
                         cudaFuncAttributeMaxDynamicSharedMemorySize, EDGE_SMEM);
    cudaFuncSetAttribute(node_kernel,
                         cudaFuncAttributeMaxDynamicSharedMemorySize, NODE_SMEM);

    zero_kernel<<<2048, 256>>>(N * 32, B * 32);
    edge_kernel<<<(E + TILE - 1) / TILE, 256, EDGE_SMEM>>>(
        edge_feat, node_feat, g_repr, src, dst, e2g,
        W_e1, b_e1, W_e2, b_e2, e_out, E);
    node_kernel<<<(N + TILE - 1) / TILE, 256, NODE_SMEM>>>(
        node_feat, g_repr, n2g, W_n1, b_n1, W_n2, b_n2, n_out, N);
    global_kernel<<<1, B * 64>>>(g_repr, W_u1, b_u1, W_u2, b_u2, g_out, B);
}

// round 7
// speedup vs baseline: 48.8383x; 1.8020x over previous
#include <cuda_runtime.h>
#include <cuda_bf16.h>
#include <cstdint>
#include <cstddef>

// ===========================================================================
// MEGNet block. Edge MLP on HMMA (mma.sync bf16, split-bf16 x3 for fp32
// accuracy), node MLP on tuned FFMA, tiny global MLP.
// tcgen05 is NOT available (harness compiles via compute_103 PTX).
// ===========================================================================

#define NMAX 50000
#define BMAX 64
#define TILE 128

__device__ __align__(16) float d_hbuf[(size_t)NMAX * 32];
__device__ __align__(16) float d_ecomb[BMAX * 32];
__device__ __align__(16) float d_ncomb[BMAX * 32];

__global__ void zero_kernel(int n_h, int n_c) {
    int stride = gridDim.x * blockDim.x;
    for (int i = blockIdx.x * blockDim.x + threadIdx.x; i < n_h; i += stride)
        d_hbuf[i] = 0.0f;
    int i = blockIdx.x * blockDim.x + threadIdx.x;
    if (i < n_c) { d_ecomb[i] = 0.0f; d_ncomb[i] = 0.0f; }
}

// ---------------------------------------------------------------------------
__device__ __forceinline__ uint32_t smem_u32(const void* p) {
    uint32_t a;
    asm("{ .reg .u64 t; cvta.to.shared.u64 t, %1; cvt.u32.u64 %0, t; }"
        : "=r"(a) : "l"(p));
    return a;
}

__device__ __forceinline__ void ldm4(uint32_t a[4], uint32_t addr) {
    asm volatile(
        "ldmatrix.sync.aligned.m8n8.x4.shared.b16 {%0,%1,%2,%3}, [%4];"
        : "=r"(a[0]), "=r"(a[1]), "=r"(a[2]), "=r"(a[3]) : "r"(addr));
}

__device__ __forceinline__ void mma16816(float c[4], const uint32_t a[4],
                                         uint2 b) {
    asm volatile(
        "mma.sync.aligned.m16n8k16.row.col.f32.bf16.bf16.f32 "
        "{%0,%1,%2,%3},{%4,%5,%6,%7},{%8,%9},{%0,%1,%2,%3};"
        : "+f"(c[0]), "+f"(c[1]), "+f"(c[2]), "+f"(c[3])
        : "r"(a[0]), "r"(a[1]), "r"(a[2]), "r"(a[3]), "r"(b.x), "r"(b.y));
}

// split fp32 pair -> bf16x2 hi and bf16x2 lo (lo = rounding residual)
__device__ __forceinline__ void split2(float a, float b, uint32_t& hi,
                                       uint32_t& lo) {
    __nv_bfloat16 ha = __float2bfloat16(a), hb = __float2bfloat16(b);
    float ra = a - __bfloat162float(ha);
    float rb = b - __bfloat162float(hb);
    __nv_bfloat16 la = __float2bfloat16(ra), lb = __float2bfloat16(rb);
    hi = ((uint32_t)__bfloat16_as_ushort(hb) << 16) | __bfloat16_as_ushort(ha);
    lo = ((uint32_t)__bfloat16_as_ushort(lb) << 16) | __bfloat16_as_ushort(la);
}

// pack two fp32 as bf16x2, hi part (low=false) or residual part (low=true)
__device__ __forceinline__ uint32_t pack_split(float a, float b, bool low) {
    __nv_bfloat16 ah = __float2bfloat16(a), bh = __float2bfloat16(b);
    if (low) {
        float ra = a - __bfloat162float(ah);
        float rb = b - __bfloat162float(bh);
        ah = __float2bfloat16(ra);
        bh = __float2bfloat16(rb);
    }
    return (uint32_t)__bfloat16_as_ushort(ah) |
           ((uint32_t)__bfloat16_as_ushort(bh) << 16);
}

// ---------------------------------------------------------------------------
// Edge kernel SMEM map (bytes):
//  0      Xhi [128][136] bf16 (34816)      } overlaid after L1:
//  34816  Xlo [128][136] bf16 (34816)      }  Hhi[128][72]@0, Hlo@18432,
//                                             S[128][36] f32 @36864 (18432)
//  69632  W1frag [16 ksteps][8 n8][32 lanes] uint2 (32768)
//  102400 W2frag [8 ksteps][4 n8][32 lanes] uint2 (8192)
//  110592 b1[64] f32 ; 110848 b2[32] f32
//  110976 ssrc[128] ; 111488 sdst[128] ; 112000 sg[128]
//  total 112640
// ---------------------------------------------------------------------------
#define OFF_XHI 0
#define OFF_XLO 34816
#define OFF_HHI 0
#define OFF_HLO 18432
#define OFF_S   36864
#define OFF_W1F 69632
#define OFF_W2F 102400
#define OFF_B1  110592
#define OFF_B2  110848
#define OFF_SRC 110976
#define OFF_DST 111488
#define OFF_G   112000
#define EDGE_SMEM 112640

__global__ __launch_bounds__(256, 1) void edge_kernel_mma(
    const float* __restrict__ edge_feat, const float* __restrict__ node_feat,
    const float* __restrict__ g_repr, const int* __restrict__ src,
    const int* __restrict__ dst, const int* __restrict__ e2g,
    const float* __restrict__ W1, const float* __restrict__ b1,
    const float* __restrict__ W2, const float* __restrict__ b2,
    float* __restrict__ e_out, int E) {
    extern __shared__ char smem[];
    const uint32_t sbase = smem_u32(smem);
    const int tid = threadIdx.x;
    const int lane = tid & 31;
    const int w = tid >> 5;
    const int m0 = (w >> 1) * 32;   // layer1/2 M offset of this warp
    const int n0 = (w & 1) * 32;    // layer1 N offset
    const int n0b = (w & 1) * 16;   // layer2 N offset

    uint2* W1f = (uint2*)(smem + OFF_W1F);
    uint2* W2f = (uint2*)(smem + OFF_W2F);
    float* b1s = (float*)(smem + OFF_B1);
    float* b2s = (float*)(smem + OFF_B2);
    int* ssrc = (int*)(smem + OFF_SRC);
    int* sdst = (int*)(smem + OFF_DST);
    int* sg   = (int*)(smem + OFF_G);
    float* S  = (float*)(smem + OFF_S);

    // ---- stage weight fragments (once per CTA) ----
    // W1frag[s][nt][l]: s 0-7 = hi k-chunks (k0=16s), s 8-15 = lo k-chunks.
    // reg.x = {B[ke][n], B[ke+1][n]}, reg.y = {B[ke+8][n], B[ke+9][n]},
    // ke = k0 + (l&3)*2, n = nt*8 + (l>>2).   W1 is [128][64] row-major.
    for (int i = tid; i < 16 * 8 * 32; i += 256) {
        int s = i >> 8, rem = i & 255, nt = rem >> 5, l = rem & 31;
        int kb = (s & 7) * 16;
        bool low = s >= 8;
        int n = nt * 8 + (l >> 2);
        int ke = kb + (l & 3) * 2;
        uint32_t x = pack_split(W1[ke * 64 + n], W1[(ke + 1) * 64 + n], low);
        uint32_t y = pack_split(W1[(ke + 8) * 64 + n], W1[(ke + 9) * 64 + n], low);
        W1f[i] = make_uint2(x, y);
    }
    // W2frag: s 0-3 hi (k0=16s), 4-7 lo. W2 is [64][32] row-major.
    for (int i = tid; i < 8 * 4 * 32; i += 256) {
        int s = i >> 7, rem = i & 127, nt = rem >> 5, l = rem & 31;
        int kb = (s & 3) * 16;
        bool low = s >= 4;
        int n = nt * 8 + (l >> 2);
        int ke = kb + (l & 3) * 2;
        uint32_t x = pack_split(W2[ke * 32 + n], W2[(ke + 1) * 32 + n], low);
        uint32_t y = pack_split(W2[(ke + 8) * 32 + n], W2[(ke + 9) * 32 + n], low);
        W2f[i] = make_uint2(x, y);
    }
    if (tid < 64) b1s[tid] = b1[tid];
    if (tid < 32) b2s[tid] = b2[tid];
    __syncthreads();

    const int ntiles = (E + TILE - 1) / TILE;
    for (int t = blockIdx.x; t < ntiles; t += gridDim.x) {
        const int e0 = t * TILE;
        const int rows = min(TILE, E - e0);

        // ---- indices ----
        if (tid < rows) {
            ssrc[tid] = src[e0 + tid];
            sdst[tid] = dst[e0 + tid];
            sg[tid]   = e2g[e0 + tid];
        }
        __syncthreads();

        // ---- gather + split X: [edge | nf[src] | nf[dst] | g[e2g]] ----
        for (int p = tid; p < rows * 4; p += 256) {
            int r = p >> 2, s = p & 3;
            const float* sp;
            if (s == 0)      sp = edge_feat + (size_t)(e0 + r) * 32;
            else if (s == 1) sp = node_feat + (size_t)ssrc[r] * 32;
            else if (s == 2) sp = node_feat + (size_t)sdst[r] * 32;
            else             sp = g_repr + (size_t)sg[r] * 32;
            float f[32];
#pragma unroll
            for (int q = 0; q < 8; q++) {
                float4 v = ((const float4*)sp)[q];
                f[4 * q + 0] = v.x; f[4 * q + 1] = v.y;
                f[4 * q + 2] = v.z; f[4 * q + 3] = v.w;
            }
            uint32_t hi[16], lo[16];
#pragma unroll
            for (int q = 0; q < 16; q++)
                split2(f[2 * q], f[2 * q + 1], hi[q], lo[q]);
            uint32_t* dh = (uint32_t*)(smem + OFF_XHI + r * 272 + s * 64);
            uint32_t* dl = (uint32_t*)(smem + OFF_XLO + r * 272 + s * 64);
#pragma unroll
            for (int q = 0; q < 16; q++) { dh[q] = hi[q]; dl[q] = lo[q]; }
        }
        __syncthreads();

        // ---- layer1: C1[128x64] over K'=384 ([Xhi|Xhi|Xlo]x[Whi;Wlo;Whi]) ----
        float c1[2][4][4];
#pragma unroll
        for (int mi = 0; mi < 2; mi++)
#pragma unroll
            for (int j = 0; j < 4; j++) {
                int nb = n0 + j * 8 + (lane & 3) * 2;
                c1[mi][j][0] = b1s[nb];
                c1[mi][j][1] = b1s[nb + 1];
                c1[mi][j][2] = b1s[nb];
                c1[mi][j][3] = b1s[nb + 1];
            }
        const int arow = lane & 15;
        const int acol = (lane >> 4) << 3;
#pragma unroll
        for (int ks = 0; ks < 24; ks++) {
            const uint32_t Ab = sbase + ((ks < 16) ? OFF_XHI : OFF_XLO);
            const int k0 = (ks & 7) * 16;
            const int Bs = (ks < 16) ? ks : ks - 16;
            uint32_t a0[4], a1[4];
            ldm4(a0, Ab + ((m0 + arow) * 136 + k0 + acol) * 2);
            ldm4(a1, Ab + ((m0 + 16 + arow) * 136 + k0 + acol) * 2);
#pragma unroll
            for (int j = 0; j < 4; j++) {
                uint2 b = W1f[(Bs * 8 + (n0 >> 3) + j) * 32 + lane];
                mma16816(c1[0][j], a0, b);
                mma16816(c1[1][j], a1, b);
            }
        }
        __syncthreads();  // all X reads done before H overlay

        // ---- relu + split -> Hhi/Hlo (bf16 [128][72]) ----
#pragma unroll
        for (int mi = 0; mi < 2; mi++)
#pragma unroll
            for (int j = 0; j < 4; j++) {
                int rA = m0 + mi * 16 + (lane >> 2);
                int n = n0 + j * 8 + (lane & 3) * 2;
                uint32_t hi, lo;
                split2(fmaxf(c1[mi][j][0], 0.0f), fmaxf(c1[mi][j][1], 0.0f),
                       hi, lo);
                *(uint32_t*)(smem + OFF_HHI + (rA * 72 + n) * 2) = hi;
                *(uint32_t*)(smem + OFF_HLO + (rA * 72 + n) * 2) = lo;
                split2(fmaxf(c1[mi][j][2], 0.0f), fmaxf(c1[mi][j][3], 0.0f),
                       hi, lo);
                *(uint32_t*)(smem + OFF_HHI + ((rA + 8) * 72 + n) * 2) = hi;
                *(uint32_t*)(smem + OFF_HLO + ((rA + 8) * 72 + n) * 2) = lo;
            }
        __syncthreads();

        // ---- layer2: C2[128x32] over K'=192 ([Hhi|Hhi|Hlo]x[W2hi;W2lo;W2hi]) ----
        float c2[2][2][4];
#pragma unroll
        for (int mi = 0; mi < 2; mi++)
#pragma unroll
            for (int j = 0; j < 2; j++) {
                int nb = n0b + j * 8 + (lane & 3) * 2;
                c2[mi][j][0] = b2s[nb];
                c2[mi][j][1] = b2s[nb + 1];
                c2[mi][j][2] = b2s[nb];
                c2[mi][j][3] = b2s[nb + 1];
            }
#pragma unroll
        for (int ks = 0; ks < 12; ks++) {
            const uint32_t Ab = sbase + ((ks < 8) ? OFF_HHI : OFF_HLO);
            const int k0 = (ks & 3) * 16;
            const int Bs = (ks < 8) ? ks : ks - 8;
            uint32_t a0[4], a1[4];
            ldm4(a0, Ab + ((m0 + arow) * 72 + k0 + acol) * 2);
            ldm4(a1, Ab + ((m0 + 16 + arow) * 72 + k0 + acol) * 2);
#pragma unroll
            for (int j = 0; j < 2; j++) {
                uint2 b = W2f[(Bs * 4 + (n0b >> 3) + j) * 32 + lane];
                mma16816(c2[0][j], a0, b);
                mma16816(c2[1][j], a1, b);
            }
        }

        // ---- C2 -> S [128][36] f32 (no overlap with H; no sync needed) ----
#pragma unroll
        for (int mi = 0; mi < 2; mi++)
#pragma unroll
            for (int j = 0; j < 2; j++) {
                int rA = m0 + mi * 16 + (lane >> 2);
                int n = n0b + j * 8 + (lane & 3) * 2;
                *(float2*)&S[rA * 36 + n] =
                    make_float2(c2[mi][j][0], c2[mi][j][1]);
                *(float2*)&S[(rA + 8) * 36 + n] =
                    make_float2(c2[mi][j][2], c2[mi][j][3]);
            }
        __syncthreads();

        // ---- epilogue: e_out store, h scatter, e_comb tile reduce ----
        for (int p = tid; p < rows * 8; p += 256) {
            int r = p >> 3, q = p & 7;
            ((float4*)(e_out + (size_t)(e0 + r) * 32))[q] =
                *(float4*)&S[r * 36 + q * 4];
        }
        for (int p = tid; p < rows * 32; p += 256) {
            int r = p >> 5, j = p & 31;
            atomicAdd(&d_hbuf[(size_t)sdst[r] * 32 + j], S[r * 36 + j]);
        }
        if (tid < 32) {
            int g0 = sg[0];
            int g1 = sg[rows - 1];
            for (int g = g0; g <= g1; g++) {
                float s = 0.0f;
                for (int r = 0; r < rows; r++)
                    if (sg[r] == g) s += S[r * 36 + tid];
                atomicAdd(&d_ecomb[g * 32 + tid], s);
            }
        }
        __syncthreads();  // protect idx/S before next tile
    }
}

// ---------------------------------------------------------------------------
// Node kernel (FFMA, proven R4 version). K=96 (nf | h | g[n2g]).
// ---------------------------------------------------------------------------
__global__ __launch_bounds__(256) void node_kernel(
    const float* __restrict__ node_feat, const float* __restrict__ g_repr,
    const int* __restrict__ n2g, const float* __restrict__ W1,
    const float* __restrict__ b1, const float* __restrict__ W2,
    const float* __restrict__ b2, float* __restrict__ n_out, int N) {
    extern __shared__ float smemf[];
    const int KPAD = 100;
    float* X   = smemf;
    float* W1s = X + 128 * KPAD;
    float* W2s = W1s + 96 * 64;
    float* b1s = W2s + 64 * 32;
    float* b2s = b1s + 64;
    int*   idx = (int*)(b2s + 32);
    float* Hs  = X;
    float* S   = X + 8704;

    const int tid = threadIdx.x;
    const int n0 = blockIdx.x * TILE;
    const int rows = min(TILE, N - n0);

    for (int t = tid; t < rows; t += 256) idx[t] = n2g[n0 + t];
    for (int t = tid; t < 96 * 64; t += 256) W1s[t] = W1[t];
    for (int t = tid; t < 64 * 32; t += 256) W2s[t] = W2[t];
    if (tid < 64) b1s[tid] = b1[tid];
    if (tid < 32) b2s[tid] = b2[tid];
    __syncthreads();

    for (int p = tid; p < rows * 3; p += 256) {
        int r = p / 3, s = p % 3;
        const float* sp;
        if (s == 0)      sp = node_feat + (size_t)(n0 + r) * 32;
        else if (s == 1) sp = d_hbuf + (size_t)(n0 + r) * 32;
        else             sp = g_repr + (size_t)idx[r] * 32;
        float* dp = X + r * KPAD + s * 32;
#pragma unroll
        for (int q = 0; q < 8; q++)
            ((float4*)dp)[q] = ((const float4*)sp)[q];
    }
    __syncthreads();

    const int tx = tid & 7;
    const int ty = tid >> 3;
    float acc[4][8];
#pragma unroll
    for (int i = 0; i < 4; i++)
#pragma unroll
        for (int c = 0; c < 8; c++) acc[i][c] = b1s[tx * 8 + c];

#pragma unroll 8
    for (int k = 0; k < 96; k++) {
        float a0 = X[(ty * 4 + 0) * KPAD + k];
        float a1 = X[(ty * 4 + 1) * KPAD + k];
        float a2 = X[(ty * 4 + 2) * KPAD + k];
        float a3 = X[(ty * 4 + 3) * KPAD + k];
        float4 w0 = *(const float4*)&W1s[k * 64 + tx * 8];
        float4 w1 = *(const float4*)&W1s[k * 64 + tx * 8 + 4];
        const float wv[8] = {w0.x, w0.y, w0.z, w0.w, w1.x, w1.y, w1.z, w1.w};
#pragma unroll
        for (int c = 0; c < 8; c++) {
            acc[0][c] = fmaf(a0, wv[c], acc[0][c]);
            acc[1][c] = fmaf(a1, wv[c], acc[1][c]);
            acc[2][c] = fmaf(a2, wv[c], acc[2][c]);
            acc[3][c] = fmaf(a3, wv[c], acc[3][c]);
        }
    }
    __syncthreads();

#pragma unroll
    for (int i = 0; i < 4; i++) {
        float* hp = Hs + (ty * 4 + i) * 68 + tx * 8;
#pragma unroll
        for (int c = 0; c < 8; c++) hp[c] = fmaxf(acc[i][c], 0.0f);
    }
    __syncthreads();

    const int tx2 = tid & 7;
    const int ty2 = tid >> 3;
    float acc2[4][4];
#pragma unroll
    for (int i = 0; i < 4; i++)
#pragma unroll
        for (int c = 0; c < 4; c++) acc2[i][c] = b2s[tx2 * 4 + c];

#pragma unroll 8
    for (int k = 0; k < 64; k++) {
        float a0 = Hs[(ty2 * 4 + 0) * 68 + k];
        float a1 = Hs[(ty2 * 4 + 1) * 68 + k];
        float a2 = Hs[(ty2 * 4 + 2) * 68 + k];
        float a3 = Hs[(ty2 * 4 + 3) * 68 + k];
        float4 w = *(const float4*)&W2s[k * 32 + tx2 * 4];
        const float wv[4] = {w.x, w.y, w.z, w.w};
#pragma unroll
        for (int c = 0; c < 4; c++) {
            acc2[0][c] = fmaf(a0, wv[c], acc2[0][c]);
            acc2[1][c] = fmaf(a1, wv[c], acc2[1][c]);
            acc2[2][c] = fmaf(a2, wv[c], acc2[2][c]);
            acc2[3][c] = fmaf(a3, wv[c], acc2[3][c]);
        }
    }
#pragma unroll
    for (int i = 0; i < 4; i++) {
        float4 v;
        v.x = acc2[i][0]; v.y = acc2[i][1]; v.z = acc2[i][2]; v.w = acc2[i][3];
        *(float4*)&S[(ty2 * 4 + i) * 32 + tx2 * 4] = v;
    }
    __syncthreads();

    for (int t = tid; t < rows * 8; t += 256) {
        int r = t >> 3, q = t & 7;
        ((float4*)(n_out + (size_t)(n0 + r) * 32))[q] = ((float4*)S)[r * 8 + q];
    }
    if (tid < 32) {
        int g0 = idx[0];
        int g1 = idx[rows - 1];
        for (int g = g0; g <= g1; g++) {
            float s = 0.0f;
            for (int r = 0; r < rows; r++)
                if (idx[r] == g) s += S[r * 32 + tid];
            atomicAdd(&d_ncomb[g * 32 + tid], s);
        }
    }
}

// ---------------------------------------------------------------------------
__global__ void global_kernel(const float* __restrict__ g_repr,
                              const float* __restrict__ W1,
                              const float* __restrict__ b1,
                              const float* __restrict__ W2,
                              const float* __restrict__ b2,
                              float* __restrict__ g_out, int B) {
    __shared__ float u[BMAX * 96];
    __shared__ float hh[BMAX * 64];
    int tid = threadIdx.x;
    for (int i = tid; i < B * 32; i += blockDim.x) {
        int r = i / 32, j = i % 32;
        u[r * 96 + j] = d_ncomb[i];
        u[r * 96 + 32 + j] = d_ecomb[i];
        u[r * 96 + 64 + j] = g_repr[i];
    }
    __syncthreads();
    if (tid < B * 64) {
        int r = tid / 64, j = tid % 64;
        float acc = b1[j];
        for (int k = 0; k < 96; k++) acc = fmaf(u[r * 96 + k], W1[k * 64 + j], acc);
        hh[r * 64 + j] = fmaxf(acc, 0.0f);
    }
    __syncthreads();
    if (tid < B * 32) {
        int r = tid / 32, j = tid % 32;
        float acc = b2[j];
        for (int k = 0; k < 64; k++) acc = fmaf(hh[r * 64 + k], W2[k * 32 + j], acc);
        g_out[tid] = acc;
    }
}

// ---------------------------------------------------------------------------
extern "C" void kernel_launch(void* const* d_in, const int* in_sizes, int n_in,
                              void* d_out, int out_size) {
    const float* edge_feat = (const float*)d_in[0];
    const float* node_feat = (const float*)d_in[1];
    const float* g_repr    = (const float*)d_in[2];
    const int*   src       = (const int*)d_in[3];
    const int*   dst       = (const int*)d_in[4];
    const int*   n2g       = (const int*)d_in[5];
    const int*   e2g       = (const int*)d_in[6];
    const float* W_e1 = (const float*)d_in[7];
    const float* b_e1 = (const float*)d_in[8];
    const float* W_e2 = (const float*)d_in[9];
    const float* b_e2 = (const float*)d_in[10];
    const float* W_n1 = (const float*)d_in[11];
    const float* b_n1 = (const float*)d_in[12];
    const float* W_n2 = (const float*)d_in[13];
    const float* b_n2 = (const float*)d_in[14];
    const float* W_u1 = (const float*)d_in[15];
    const float* b_u1 = (const float*)d_in[16];
    const float* W_u2 = (const float*)d_in[17];
    const float* b_u2 = (const float*)d_in[18];

    int E = in_sizes[3];
    int N = in_sizes[5];
    int B = in_sizes[2] / 32;

    float* e_out = (float*)d_out;
    float* n_out = e_out + (size_t)E * 32;
    float* g_out = n_out + (size_t)N * 32;

    const int NODE_SMEM = 84864;
    cudaFuncSetAttribute(edge_kernel_mma,
                         cudaFuncAttributeMaxDynamicSharedMemorySize, EDGE_SMEM);
    cudaFuncSetAttribute(node_kernel,
                         cudaFuncAttributeMaxDynamicSharedMemorySize, NODE_SMEM);

    zero_kernel<<<2048, 256>>>(N * 32, B * 32);
    edge_kernel_mma<<<148, 256, EDGE_SMEM>>>(
        edge_feat, node_feat, g_repr, src, dst, e2g,
        W_e1, b_e1, W_e2, b_e2, e_out, E);
    node_kernel<<<(N + TILE - 1) / TILE, 256, NODE_SMEM>>>(
        node_feat, g_repr, n2g, W_n1, b_n1, W_n2, b_n2, n_out, N);
    global_kernel<<<1, B * 64>>>(g_repr, W_u1, b_u1, W_u2, b_u2, g_out, B);
}